// round 3
// baseline (speedup 1.0000x reference)
#include <cuda_runtime.h>

// Problem constants
#define Bv 32
#define Av 1024
#define NNv 5
#define F_INv 128
#define E0v 128
#define E1v 32
#define NACTv 8
#define ROWS (Bv * Av)            // 32768
#define CHUNKS (ROWS / 4)         // 8192 chunks of 4 rows

#define NTHREADS 512
#define GRID 152

// dynamic smem layout, offsets in floats
#define OFF_WE0 0          // 128*128 = 16384
#define OFF_WE1 16384      // 128*32  = 4096
#define OFF_W1  20480      // 32*32
#define OFF_W2  21504
#define OFF_W3  22528
#define OFF_W4P 23552      // [8][32] fused W4@Wp, transposed
#define OFF_BE0 23808      // 128
#define OFF_BE1 23936      // 32
#define OFF_B1  23968
#define OFF_B2  24000
#define OFF_B3  24032
#define OFF_B4P 24064      // 8
#define OFF_XBUF 24096     // 16 warps * 512 floats (4 rows x 128)
#define SMEM_FLOATS (24096 + 16*512)   // 32288
#define SMEM_BYTES (SMEM_FLOATS * 4)

__device__ unsigned int g_ctr;

__device__ __forceinline__ float warpsum(float v) {
    v += __shfl_xor_sync(0xffffffffu, v, 16);
    v += __shfl_xor_sync(0xffffffffu, v, 8);
    v += __shfl_xor_sync(0xffffffffu, v, 4);
    v += __shfl_xor_sync(0xffffffffu, v, 2);
    v += __shfl_xor_sync(0xffffffffu, v, 1);
    return v;
}

__device__ __forceinline__ void fma4(float4& a, float s, const float4& w) {
    a.x = fmaf(s, w.x, a.x);
    a.y = fmaf(s, w.y, a.y);
    a.z = fmaf(s, w.z, a.z);
    a.w = fmaf(s, w.w, a.w);
}

__global__ __launch_bounds__(NTHREADS, 1) void fused_kernel(
    const float* __restrict__ x,
    const float* __restrict__ y,
    const float* __restrict__ We0, const float* __restrict__ be0,
    const float* __restrict__ We1, const float* __restrict__ be1,
    const float* __restrict__ W1, const float* __restrict__ b1,
    const float* __restrict__ W2, const float* __restrict__ b2,
    const float* __restrict__ W3, const float* __restrict__ b3,
    const float* __restrict__ W4, const float* __restrict__ b4,
    const float* __restrict__ Wp, const float* __restrict__ bp,
    float* __restrict__ out)
{
    extern __shared__ float sm[];
    const int tid  = threadIdx.x;
    const int lane = tid & 31;
    const int w    = tid >> 5;

    // ---- cooperative weight load into smem ----
    for (int i = tid; i < 16384; i += NTHREADS) sm[OFF_WE0 + i] = We0[i];
    for (int i = tid; i < 4096;  i += NTHREADS) sm[OFF_WE1 + i] = We1[i];
    for (int i = tid; i < 1024;  i += NTHREADS) {
        sm[OFF_W1 + i] = W1[i];
        sm[OFF_W2 + i] = W2[i];
        sm[OFF_W3 + i] = W3[i];
    }
    // fused head: W4p[a][e] = sum_k W4[e][k]*Wp[k][a]; b4p[a] = b4@Wp + bp
    if (tid < 256) {
        const int a = tid >> 5, e = tid & 31;
        float acc = 0.f;
        #pragma unroll 8
        for (int k = 0; k < 32; k++)
            acc = fmaf(W4[e * 32 + k], Wp[k * NACTv + a], acc);
        sm[OFF_W4P + a * 32 + e] = acc;
    }
    if (tid < 128) sm[OFF_BE0 + tid] = be0[tid];
    if (tid < 32) {
        sm[OFF_BE1 + tid] = be1[tid];
        sm[OFF_B1 + tid] = b1[tid];
        sm[OFF_B2 + tid] = b2[tid];
        sm[OFF_B3 + tid] = b3[tid];
        if (tid < 8) {
            float acc = bp[tid];
            #pragma unroll 8
            for (int k = 0; k < 32; k++)
                acc = fmaf(b4[k], Wp[k * NACTv + tid], acc);
            sm[OFF_B4P + tid] = acc;
        }
    }
    __syncthreads();

    const float4* We0s4 = (const float4*)(sm + OFF_WE0);
    const float4* be0s4 = (const float4*)(sm + OFF_BE0);
    float4* xb4 = (float4*)(sm + OFF_XBUF) + w * 128;   // 4 rows x 32 float4

    const float b1v = sm[OFF_B1 + lane];
    const float b2v = sm[OFF_B2 + lane];
    const float b3v = sm[OFF_B3 + lane];
    const float be1v = sm[OFF_BE1 + lane];

    // ---- warp-level work stealing over 4-row chunks ----
    for (;;) {
        unsigned int c;
        if (lane == 0) c = atomicAdd(&g_ctr, 1u);
        c = __shfl_sync(0xffffffffu, c, 0);
        if (c >= CHUNKS) break;
        const int row0 = (int)c * 4;

        // ---- stage x (4 rows) into per-warp smem ----
        #pragma unroll
        for (int r = 0; r < 4; r++)
            xb4[r * 32 + lane] = ((const float4*)(x + (size_t)(row0 + r) * F_INv))[lane];
        __syncwarp();

        // ---- y accumulation: ALL 160 LDG.128 in one straight-line region,
        //      no warp reductions in between (deferred to the end) ----
        const float4* yb = (const float4*)(y + (size_t)row0 * (NNv * Av));
        float s[4][NNv];
        #pragma unroll
        for (int r = 0; r < 4; r++)
            #pragma unroll
            for (int n = 0; n < NNv; n++) s[r][n] = 0.f;

        #pragma unroll
        for (int r = 0; r < 4; r++)
            #pragma unroll
            for (int n = 0; n < NNv; n++)
                #pragma unroll
                for (int i = 0; i < 8; i++) {
                    float4 v = yb[r * 1280 + n * 256 + i * 32 + lane];
                    s[r][n] += (v.x + v.y) + (v.z + v.w);
                }

        // ---- layer 0 (overlaps with in-flight y loads): 4 rows,
        //      lane owns features lane*4..lane*4+3 ----
        float4 acc0 = be0s4[lane], acc1 = acc0, acc2 = acc0, acc3 = acc0;
        #pragma unroll 8
        for (int k4 = 0; k4 < 32; k4++) {
            float4 w0 = We0s4[(k4 * 4 + 0) * 32 + lane];
            float4 w1 = We0s4[(k4 * 4 + 1) * 32 + lane];
            float4 w2 = We0s4[(k4 * 4 + 2) * 32 + lane];
            float4 w3 = We0s4[(k4 * 4 + 3) * 32 + lane];
            float4 xk;
            xk = xb4[0 * 32 + k4];
            fma4(acc0, xk.x, w0); fma4(acc0, xk.y, w1); fma4(acc0, xk.z, w2); fma4(acc0, xk.w, w3);
            xk = xb4[1 * 32 + k4];
            fma4(acc1, xk.x, w0); fma4(acc1, xk.y, w1); fma4(acc1, xk.z, w2); fma4(acc1, xk.w, w3);
            xk = xb4[2 * 32 + k4];
            fma4(acc2, xk.x, w0); fma4(acc2, xk.y, w1); fma4(acc2, xk.z, w2); fma4(acc2, xk.w, w3);
            xk = xb4[3 * 32 + k4];
            fma4(acc3, xk.x, w0); fma4(acc3, xk.y, w1); fma4(acc3, xk.z, w2); fma4(acc3, xk.w, w3);
        }
        __syncwarp();
        acc0.x = fmaxf(acc0.x, 0.f); acc0.y = fmaxf(acc0.y, 0.f); acc0.z = fmaxf(acc0.z, 0.f); acc0.w = fmaxf(acc0.w, 0.f);
        acc1.x = fmaxf(acc1.x, 0.f); acc1.y = fmaxf(acc1.y, 0.f); acc1.z = fmaxf(acc1.z, 0.f); acc1.w = fmaxf(acc1.w, 0.f);
        acc2.x = fmaxf(acc2.x, 0.f); acc2.y = fmaxf(acc2.y, 0.f); acc2.z = fmaxf(acc2.z, 0.f); acc2.w = fmaxf(acc2.w, 0.f);
        acc3.x = fmaxf(acc3.x, 0.f); acc3.y = fmaxf(acc3.y, 0.f); acc3.z = fmaxf(acc3.z, 0.f); acc3.w = fmaxf(acc3.w, 0.f);
        xb4[0 * 32 + lane] = acc0;
        xb4[1 * 32 + lane] = acc1;
        xb4[2 * 32 + lane] = acc2;
        xb4[3 * 32 + lane] = acc3;
        __syncwarp();

        // ---- layer 1: lane owns output dim `lane` ----
        float a1_0 = be1v, a1_1 = be1v, a1_2 = be1v, a1_3 = be1v;
        #pragma unroll 8
        for (int k4 = 0; k4 < 32; k4++) {
            float w0 = sm[OFF_WE1 + (k4 * 4 + 0) * 32 + lane];
            float w1 = sm[OFF_WE1 + (k4 * 4 + 1) * 32 + lane];
            float w2 = sm[OFF_WE1 + (k4 * 4 + 2) * 32 + lane];
            float w3 = sm[OFF_WE1 + (k4 * 4 + 3) * 32 + lane];
            float4 hk;
            hk = xb4[0 * 32 + k4];
            a1_0 = fmaf(hk.x, w0, a1_0); a1_0 = fmaf(hk.y, w1, a1_0); a1_0 = fmaf(hk.z, w2, a1_0); a1_0 = fmaf(hk.w, w3, a1_0);
            hk = xb4[1 * 32 + k4];
            a1_1 = fmaf(hk.x, w0, a1_1); a1_1 = fmaf(hk.y, w1, a1_1); a1_1 = fmaf(hk.z, w2, a1_1); a1_1 = fmaf(hk.w, w3, a1_1);
            hk = xb4[2 * 32 + k4];
            a1_2 = fmaf(hk.x, w0, a1_2); a1_2 = fmaf(hk.y, w1, a1_2); a1_2 = fmaf(hk.z, w2, a1_2); a1_2 = fmaf(hk.w, w3, a1_2);
            hk = xb4[3 * 32 + k4];
            a1_3 = fmaf(hk.x, w0, a1_3); a1_3 = fmaf(hk.y, w1, a1_3); a1_3 = fmaf(hk.z, w2, a1_3); a1_3 = fmaf(hk.w, w3, a1_3);
        }
        float h[4];
        h[0] = fmaxf(a1_0, 0.f); h[1] = fmaxf(a1_1, 0.f);
        h[2] = fmaxf(a1_2, 0.f); h[3] = fmaxf(a1_3, 0.f);

        // ---- g1/g2/g3 = h@W1..W3 for all 4 rows ----
        float g1[4], g2[4], g3[4];
        #pragma unroll
        for (int r = 0; r < 4; r++) { g1[r] = b1v; g2[r] = 0.f; g3[r] = 0.f; }
        #pragma unroll 8
        for (int e = 0; e < 32; e++) {
            const float w1e = sm[OFF_W1 + e * 32 + lane];
            const float w2e = sm[OFF_W2 + e * 32 + lane];
            const float w3e = sm[OFF_W3 + e * 32 + lane];
            #pragma unroll
            for (int r = 0; r < 4; r++) {
                const float he = __shfl_sync(0xffffffffu, h[r], e);
                g1[r] = fmaf(he, w1e, g1[r]);
                g2[r] = fmaf(he, w2e, g2[r]);
                g3[r] = fmaf(he, w3e, g3[r]);
            }
        }
        #pragma unroll
        for (int r = 0; r < 4; r++) g1[r] = fmaxf(g1[r], 0.f);

        // ---- deferred warp reductions for ys ----
        float ys[4][NNv];
        #pragma unroll
        for (int r = 0; r < 4; r++)
            #pragma unroll
            for (int n = 0; n < NNv; n++)
                ys[r][n] = warpsum(s[r][n]);

        // ---- per-row epilogue ----
        #pragma unroll
        for (int r = 0; r < 4; r++) {
            const int row = row0 + r;

            float sc[NNv];
            #pragma unroll
            for (int n = 0; n < NNv; n++)
                sc[n] = g1[r] * fmaxf(fmaf(ys[r][n], g2[r], b2v), 0.0f);
            #pragma unroll
            for (int n = 0; n < NNv; n++)
                sc[n] = warpsum(sc[n]);

            float m = sc[0];
            #pragma unroll
            for (int n = 1; n < NNv; n++) m = fmaxf(m, sc[n]);
            float att[NNv], denom = 0.0f;
            #pragma unroll
            for (int n = 0; n < NNv; n++) { att[n] = __expf(sc[n] - m); denom += att[n]; }
            const float inv = 1.0f / denom;
            float sv = 0.0f;
            #pragma unroll
            for (int n = 0; n < NNv; n++) { att[n] *= inv; sv = fmaf(att[n], ys[r][n], sv); }

            // ctx_d = s*g3_d + b3_d; logits = ctx @ W4p^T + b4p (fused head)
            const float ctxd = fmaf(sv, g3[r], b3v);
            float la = 0.0f;
            #pragma unroll
            for (int a = 0; a < NACTv; a++) {
                float p = warpsum(ctxd * sm[OFF_W4P + a * 32 + lane]);
                if (lane == a) la = p;
            }
            if (lane < NACTv)
                out[(size_t)row * NACTv + lane] = la + sm[OFF_B4P + lane];

            float av = 0.0f;
            #pragma unroll
            for (int n = 0; n < NNv; n++) if (lane == n) av = att[n];
            if (lane < NNv)
                out[(size_t)ROWS * NACTv + (size_t)row * NNv + lane] = av;
        }
    }
}

// ---------------------------------------------------------------------------
extern "C" void kernel_launch(void* const* d_in, const int* in_sizes, int n_in,
                              void* d_out, int out_size)
{
    const float* x   = (const float*)d_in[0];
    const float* y   = (const float*)d_in[1];
    const float* We0 = (const float*)d_in[2];
    const float* be0 = (const float*)d_in[3];
    const float* We1 = (const float*)d_in[4];
    const float* be1 = (const float*)d_in[5];
    const float* W1  = (const float*)d_in[6];
    const float* b1  = (const float*)d_in[7];
    const float* W2  = (const float*)d_in[8];
    const float* b2  = (const float*)d_in[9];
    const float* W3  = (const float*)d_in[10];
    const float* b3  = (const float*)d_in[11];
    const float* W4  = (const float*)d_in[12];
    const float* b4  = (const float*)d_in[13];
    const float* Wp  = (const float*)d_in[14];
    const float* bp  = (const float*)d_in[15];
    float* out = (float*)d_out;

    cudaFuncSetAttribute(fused_kernel, cudaFuncAttributeMaxDynamicSharedMemorySize, SMEM_BYTES);

    void* ctr_ptr = nullptr;
    cudaGetSymbolAddress(&ctr_ptr, g_ctr);
    cudaMemsetAsync(ctr_ptr, 0, sizeof(unsigned int));

    fused_kernel<<<GRID, NTHREADS, SMEM_BYTES>>>(
        x, y, We0, be0, We1, be1, W1, b1, W2, b2, W3, b3, W4, b4, Wp, bp, out);
}

// round 4
// speedup vs baseline: 1.0120x; 1.0120x over previous
#include <cuda_runtime.h>

// Problem constants
#define Bv 32
#define Av 1024
#define NNv 5
#define F_INv 128
#define E0v 128
#define E1v 32
#define NACTv 8
#define ROWS (Bv * Av)            // 32768
#define CHUNKS (ROWS / 4)         // 8192 chunks of 4 rows

#define NTHREADS 512
#define NWARPS 16
#define GRID 304                  // 2 blocks per SM on 152 SMs

__device__ unsigned int g_ctr;

__device__ __forceinline__ float warpsum(float v) {
    v += __shfl_xor_sync(0xffffffffu, v, 16);
    v += __shfl_xor_sync(0xffffffffu, v, 8);
    v += __shfl_xor_sync(0xffffffffu, v, 4);
    v += __shfl_xor_sync(0xffffffffu, v, 2);
    v += __shfl_xor_sync(0xffffffffu, v, 1);
    return v;
}

__device__ __forceinline__ void fma4(float4& a, float s, const float4& w) {
    a.x = fmaf(s, w.x, a.x);
    a.y = fmaf(s, w.y, a.y);
    a.z = fmaf(s, w.z, a.z);
    a.w = fmaf(s, w.w, a.w);
}

__global__ __launch_bounds__(NTHREADS, 2) void fused_kernel(
    const float* __restrict__ x,
    const float* __restrict__ y,
    const float* __restrict__ We0, const float* __restrict__ be0,
    const float* __restrict__ We1, const float* __restrict__ be1,
    const float* __restrict__ W1, const float* __restrict__ b1,
    const float* __restrict__ W2, const float* __restrict__ b2,
    const float* __restrict__ W3, const float* __restrict__ b3,
    const float* __restrict__ W4, const float* __restrict__ b4,
    const float* __restrict__ Wp, const float* __restrict__ bp,
    float* __restrict__ out)
{
    __shared__ float4 xb[NWARPS][128];   // per-warp: 4 rows x 32 float4 (x, then h1)
    __shared__ float w4ps[NACTv * 32];   // fused W4@Wp, [a][e]
    __shared__ float b4ps[NACTv];

    const int tid  = threadIdx.x;
    const int lane = tid & 31;
    const int w    = tid >> 5;

    // fused head: W4p[a][e] = sum_k W4[e][k]*Wp[k][a]; b4p[a] = b4@Wp + bp
    if (tid < 256) {
        const int a = tid >> 5, e = tid & 31;
        float acc = 0.f;
        #pragma unroll 8
        for (int k = 0; k < 32; k++)
            acc = fmaf(__ldg(&W4[e * 32 + k]), __ldg(&Wp[k * NACTv + a]), acc);
        w4ps[a * 32 + e] = acc;
        if (tid < NACTv) {
            float bacc = __ldg(&bp[tid]);
            #pragma unroll 8
            for (int k = 0; k < 32; k++)
                bacc = fmaf(__ldg(&b4[k]), __ldg(&Wp[k * NACTv + tid]), bacc);
            b4ps[tid] = bacc;
        }
    }
    __syncthreads();

    const float4* We0v = (const float4*)We0;
    const float4* be0v = (const float4*)be0;
    const float4* xv   = (const float4*)x;

    const float b1v  = __ldg(&b1[lane]);
    const float b2v  = __ldg(&b2[lane]);
    const float b3v  = __ldg(&b3[lane]);
    const float be1v = __ldg(&be1[lane]);

    // ---- warp-level work stealing over 4-row chunks ----
    for (;;) {
        unsigned int c;
        if (lane == 0) c = atomicAdd(&g_ctr, 1u);
        c = __shfl_sync(0xffffffffu, c, 0);
        if (c >= CHUNKS) break;
        const int row0 = (int)c * 4;

        // ---- stage x (4 rows, streaming) into per-warp smem ----
        #pragma unroll
        for (int r = 0; r < 4; r++)
            xb[w][r * 32 + lane] = __ldcs(&xv[(size_t)(row0 + r) * 32 + lane]);
        __syncwarp();

        // ---- layer 0: lane owns features lane*4..lane*4+3, weights from L1 ----
        float4 acc0 = __ldg(&be0v[lane]), acc1 = acc0, acc2 = acc0, acc3 = acc0;
        #pragma unroll 4
        for (int k4 = 0; k4 < 32; k4++) {
            float4 w0 = __ldg(&We0v[(k4 * 4 + 0) * 32 + lane]);
            float4 w1 = __ldg(&We0v[(k4 * 4 + 1) * 32 + lane]);
            float4 w2 = __ldg(&We0v[(k4 * 4 + 2) * 32 + lane]);
            float4 w3 = __ldg(&We0v[(k4 * 4 + 3) * 32 + lane]);
            float4 xk;
            xk = xb[w][0 * 32 + k4];
            fma4(acc0, xk.x, w0); fma4(acc0, xk.y, w1); fma4(acc0, xk.z, w2); fma4(acc0, xk.w, w3);
            xk = xb[w][1 * 32 + k4];
            fma4(acc1, xk.x, w0); fma4(acc1, xk.y, w1); fma4(acc1, xk.z, w2); fma4(acc1, xk.w, w3);
            xk = xb[w][2 * 32 + k4];
            fma4(acc2, xk.x, w0); fma4(acc2, xk.y, w1); fma4(acc2, xk.z, w2); fma4(acc2, xk.w, w3);
            xk = xb[w][3 * 32 + k4];
            fma4(acc3, xk.x, w0); fma4(acc3, xk.y, w1); fma4(acc3, xk.z, w2); fma4(acc3, xk.w, w3);
        }
        __syncwarp();
        acc0.x = fmaxf(acc0.x, 0.f); acc0.y = fmaxf(acc0.y, 0.f); acc0.z = fmaxf(acc0.z, 0.f); acc0.w = fmaxf(acc0.w, 0.f);
        acc1.x = fmaxf(acc1.x, 0.f); acc1.y = fmaxf(acc1.y, 0.f); acc1.z = fmaxf(acc1.z, 0.f); acc1.w = fmaxf(acc1.w, 0.f);
        acc2.x = fmaxf(acc2.x, 0.f); acc2.y = fmaxf(acc2.y, 0.f); acc2.z = fmaxf(acc2.z, 0.f); acc2.w = fmaxf(acc2.w, 0.f);
        acc3.x = fmaxf(acc3.x, 0.f); acc3.y = fmaxf(acc3.y, 0.f); acc3.z = fmaxf(acc3.z, 0.f); acc3.w = fmaxf(acc3.w, 0.f);
        xb[w][0 * 32 + lane] = acc0;
        xb[w][1 * 32 + lane] = acc1;
        xb[w][2 * 32 + lane] = acc2;
        xb[w][3 * 32 + lane] = acc3;
        __syncwarp();

        // ---- layer 1: lane owns output dim `lane` ----
        float a1_0 = be1v, a1_1 = be1v, a1_2 = be1v, a1_3 = be1v;
        #pragma unroll 4
        for (int k4 = 0; k4 < 32; k4++) {
            float w0 = __ldg(&We1[(k4 * 4 + 0) * 32 + lane]);
            float w1 = __ldg(&We1[(k4 * 4 + 1) * 32 + lane]);
            float w2 = __ldg(&We1[(k4 * 4 + 2) * 32 + lane]);
            float w3 = __ldg(&We1[(k4 * 4 + 3) * 32 + lane]);
            float4 hk;
            hk = xb[w][0 * 32 + k4];
            a1_0 = fmaf(hk.x, w0, a1_0); a1_0 = fmaf(hk.y, w1, a1_0); a1_0 = fmaf(hk.z, w2, a1_0); a1_0 = fmaf(hk.w, w3, a1_0);
            hk = xb[w][1 * 32 + k4];
            a1_1 = fmaf(hk.x, w0, a1_1); a1_1 = fmaf(hk.y, w1, a1_1); a1_1 = fmaf(hk.z, w2, a1_1); a1_1 = fmaf(hk.w, w3, a1_1);
            hk = xb[w][2 * 32 + k4];
            a1_2 = fmaf(hk.x, w0, a1_2); a1_2 = fmaf(hk.y, w1, a1_2); a1_2 = fmaf(hk.z, w2, a1_2); a1_2 = fmaf(hk.w, w3, a1_2);
            hk = xb[w][3 * 32 + k4];
            a1_3 = fmaf(hk.x, w0, a1_3); a1_3 = fmaf(hk.y, w1, a1_3); a1_3 = fmaf(hk.z, w2, a1_3); a1_3 = fmaf(hk.w, w3, a1_3);
        }
        float h[4];
        h[0] = fmaxf(a1_0, 0.f); h[1] = fmaxf(a1_1, 0.f);
        h[2] = fmaxf(a1_2, 0.f); h[3] = fmaxf(a1_3, 0.f);

        // ---- g1/g2/g3 = h@W1..W3 for all 4 rows (weights from L1) ----
        float g1[4], g2[4], g3[4];
        #pragma unroll
        for (int r = 0; r < 4; r++) { g1[r] = b1v; g2[r] = 0.f; g3[r] = 0.f; }
        #pragma unroll 4
        for (int e = 0; e < 32; e++) {
            const float w1e = __ldg(&W1[e * 32 + lane]);
            const float w2e = __ldg(&W2[e * 32 + lane]);
            const float w3e = __ldg(&W3[e * 32 + lane]);
            #pragma unroll
            for (int r = 0; r < 4; r++) {
                const float he = __shfl_sync(0xffffffffu, h[r], e);
                g1[r] = fmaf(he, w1e, g1[r]);
                g2[r] = fmaf(he, w2e, g2[r]);
                g3[r] = fmaf(he, w3e, g3[r]);
            }
        }
        #pragma unroll
        for (int r = 0; r < 4; r++) g1[r] = fmaxf(g1[r], 0.f);

        // ---- per-row: y reduction (streaming loads, n in pairs) + epilogue ----
        #pragma unroll 1
        for (int r = 0; r < 4; r++) {
            const int row = row0 + r;
            const float4* yp = (const float4*)(y + (size_t)row * (NNv * Av));
            float ys[NNv];

            // n = {0,1}: 16 loads in flight
            {
                float sA = 0.f, sB = 0.f;
                #pragma unroll
                for (int i = 0; i < 8; i++) {
                    float4 vA = __ldcs(yp + 0 * 256 + i * 32 + lane);
                    float4 vB = __ldcs(yp + 1 * 256 + i * 32 + lane);
                    sA += (vA.x + vA.y) + (vA.z + vA.w);
                    sB += (vB.x + vB.y) + (vB.z + vB.w);
                }
                ys[0] = warpsum(sA);
                ys[1] = warpsum(sB);
            }
            // n = {2,3}
            {
                float sA = 0.f, sB = 0.f;
                #pragma unroll
                for (int i = 0; i < 8; i++) {
                    float4 vA = __ldcs(yp + 2 * 256 + i * 32 + lane);
                    float4 vB = __ldcs(yp + 3 * 256 + i * 32 + lane);
                    sA += (vA.x + vA.y) + (vA.z + vA.w);
                    sB += (vB.x + vB.y) + (vB.z + vB.w);
                }
                ys[2] = warpsum(sA);
                ys[3] = warpsum(sB);
            }
            // n = 4
            {
                float sA = 0.f;
                #pragma unroll
                for (int i = 0; i < 8; i++) {
                    float4 vA = __ldcs(yp + 4 * 256 + i * 32 + lane);
                    sA += (vA.x + vA.y) + (vA.z + vA.w);
                }
                ys[4] = warpsum(sA);
            }

            float sc[NNv];
            #pragma unroll
            for (int n = 0; n < NNv; n++)
                sc[n] = warpsum(g1[r] * fmaxf(fmaf(ys[n], g2[r], b2v), 0.0f));

            float m = sc[0];
            #pragma unroll
            for (int n = 1; n < NNv; n++) m = fmaxf(m, sc[n]);
            float att[NNv], denom = 0.0f;
            #pragma unroll
            for (int n = 0; n < NNv; n++) { att[n] = __expf(sc[n] - m); denom += att[n]; }
            const float inv = 1.0f / denom;
            float sv = 0.0f;
            #pragma unroll
            for (int n = 0; n < NNv; n++) { att[n] *= inv; sv = fmaf(att[n], ys[n], sv); }

            // ctx_d = s*g3_d + b3_d; logits = ctx @ W4p^T + b4p (fused head)
            const float ctxd = fmaf(sv, g3[r], b3v);
            float la = 0.0f;
            #pragma unroll
            for (int a = 0; a < NACTv; a++) {
                float p = warpsum(ctxd * w4ps[a * 32 + lane]);
                if (lane == a) la = p;
            }
            if (lane < NACTv)
                out[(size_t)row * NACTv + lane] = la + b4ps[lane];

            float av = 0.0f;
            #pragma unroll
            for (int n = 0; n < NNv; n++) if (lane == n) av = att[n];
            if (lane < NNv)
                out[(size_t)ROWS * NACTv + (size_t)row * NNv + lane] = av;
        }
    }
}

// ---------------------------------------------------------------------------
extern "C" void kernel_launch(void* const* d_in, const int* in_sizes, int n_in,
                              void* d_out, int out_size)
{
    const float* x   = (const float*)d_in[0];
    const float* y   = (const float*)d_in[1];
    const float* We0 = (const float*)d_in[2];
    const float* be0 = (const float*)d_in[3];
    const float* We1 = (const float*)d_in[4];
    const float* be1 = (const float*)d_in[5];
    const float* W1  = (const float*)d_in[6];
    const float* b1  = (const float*)d_in[7];
    const float* W2  = (const float*)d_in[8];
    const float* b2  = (const float*)d_in[9];
    const float* W3  = (const float*)d_in[10];
    const float* b3  = (const float*)d_in[11];
    const float* W4  = (const float*)d_in[12];
    const float* b4  = (const float*)d_in[13];
    const float* Wp  = (const float*)d_in[14];
    const float* bp  = (const float*)d_in[15];
    float* out = (float*)d_out;

    void* ctr_ptr = nullptr;
    cudaGetSymbolAddress(&ctr_ptr, g_ctr);
    cudaMemsetAsync(ctr_ptr, 0, sizeof(unsigned int));

    fused_kernel<<<GRID, NTHREADS>>>(
        x, y, We0, be0, We1, be1, W1, b1, W2, b2, W3, b3, W4, b4, Wp, bp, out);
}